// round 12
// baseline (speedup 1.0000x reference)
#include <cuda_runtime.h>

// SphericalHarmonicsAttentionBias — tiled 3-phase fused kernel (sm_103a, fp32
// + packed fma.rn.f32x2).
//
// R10: the R8/R9 binder was L1 data-RETURN bandwidth (broadcast weights are
// replicated to every lane: ~8B/lane per ffma2). Fix: amortize weight bytes
// over 4 pairs per thread via a register-tiled layer-2 GEMM with activations
// staged in SMEM. Weight return drops 16B/ffma2 -> 2.5B/ffma2.
//
// CTA = 128 threads = tile of 128 pairs (fixed b,i ; j-tile of 128).
//   phase0: thread t -> pair t: SH + layer1 + SiLU -> At[64ch][128pair]
//   phase2: thread (g=t&31, c=t>>5): pairs 4g..4g+3 x channels 16c..16c+15
//           64-step k loop, 32 ffma2/step; SiLU; STS.128 back into At
//   phase3: pairs 4g..4g+3 x heads {2c,2c+1}; coalesced float4 stores.

#define S_DIM 1024
#define EPSF 1e-6f

static __device__ __forceinline__ unsigned long long pack2(float lo, float hi) {
    unsigned long long r;
    asm("mov.b64 %0, {%1, %2};" : "=l"(r) : "f"(lo), "f"(hi));
    return r;
}
static __device__ __forceinline__ void unpack2(unsigned long long v, float& lo, float& hi) {
    asm("mov.b64 {%0, %1}, %2;" : "=f"(lo), "=f"(hi) : "l"(v));
}
static __device__ __forceinline__ void ffma2(unsigned long long& d,
                                             unsigned long long a,
                                             unsigned long long b) {
    asm("fma.rn.f32x2 %0, %1, %2, %0;" : "+l"(d) : "l"(a), "l"(b));
}
static __device__ __forceinline__ float silu_f(float x) {
    return __fdividef(x, 1.0f + __expf(-x));
}

__global__ void __launch_bounds__(128, 3)
shab_kernel(const float* __restrict__ coords,
            const float* __restrict__ w1, const float* __restrict__ b1,
            const float* __restrict__ w2, const float* __restrict__ b2,
            const float* __restrict__ w3, const float* __restrict__ b3,
            float* __restrict__ out)
{
    __shared__ float At[64][128];                 // 32 KB, reused L1-out then L2-out
    __shared__ ulonglong2 w1q[9 * 16];            // 2.3 KB (quads of 4 fp32)
    __shared__ ulonglong2 w2q[64 * 16];           // 16 KB
    __shared__ unsigned long long w3d[64 * 4];    // 2 KB   (pairs of fp32)
    __shared__ ulonglong2 b1q[16];
    __shared__ ulonglong2 b2q[16];
    __shared__ unsigned long long b3d[4];

    const int tid = threadIdx.x;

    // ---- stage weights ----
    {
        const ulonglong2* g1 = (const ulonglong2*)w1;
        for (int x = tid; x < 9 * 16; x += 128) w1q[x] = g1[x];
        const ulonglong2* g2 = (const ulonglong2*)w2;
        for (int x = tid; x < 64 * 16; x += 128) w2q[x] = g2[x];
        const unsigned long long* g3 = (const unsigned long long*)w3;
        for (int x = tid; x < 64 * 4; x += 128) w3d[x] = g3[x];
        if (tid < 16)       b1q[tid]      = ((const ulonglong2*)b1)[tid];
        else if (tid < 32)  b2q[tid - 16] = ((const ulonglong2*)b2)[tid - 16];
        else if (tid < 36)  b3d[tid - 32] = ((const unsigned long long*)b3)[tid - 32];
    }

    const int i  = blockIdx.y;
    const int bb = blockIdx.z;
    const int j  = blockIdx.x * 128 + tid;
    const float* cb = coords + (size_t)bb * (S_DIM * 3);

    // ---- SH (independent of smem; overlaps weight staging) ----
    const float rx = cb[i * 3 + 0] - cb[j * 3 + 0];
    const float ry = cb[i * 3 + 1] - cb[j * 3 + 1];
    const float rz = cb[i * 3 + 2] - cb[j * 3 + 2];
    const float nrm = sqrtf(rx * rx + ry * ry + rz * rz);
    const float inv = __fdividef(1.0f, nrm + EPSF);
    float ux = rx * inv, uy = ry * inv, uz = rz * inv;
    const float un = sqrtf(ux * ux + uy * uy + uz * uz);
    const float sc = __fdividef(1.0f, fmaxf(un, EPSF));
    ux *= sc; uy *= sc; uz *= sc;

    const float C0    = 0.28209479177387814f;
    const float C1    = 0.48860251190291992f;
    const float C2    = 0.63078313050504009f;
    const float C2S3  = 1.09254843059207907f;
    const float C2S3H = 0.54627421529603953f;

    float sh[9];
    sh[0] = C0;
    sh[1] = C1 * ux;  sh[2] = C1 * uy;  sh[3] = C1 * uz;
    sh[4] = C2S3 * ux * uz;
    sh[5] = C2S3 * ux * uy;
    sh[6] = C2 * (uy * uy - 0.5f * (ux * ux + uz * uz));
    sh[7] = C2S3 * uy * uz;
    sh[8] = C2S3H * (uz * uz - ux * ux);

    __syncthreads();

    // ---- phase 0: layer 1 ([9]@[9,64]) + SiLU -> At[ch][pair] ----
    {
        unsigned long long acc[32];
#pragma unroll
        for (int q = 0; q < 16; q++) {
            const ulonglong2 bbv = b1q[q];
            acc[2 * q] = bbv.x;  acc[2 * q + 1] = bbv.y;
        }
#pragma unroll
        for (int k = 0; k < 9; k++) {
            const unsigned long long a = pack2(sh[k], sh[k]);
#pragma unroll
            for (int q = 0; q < 16; q++) {
                const ulonglong2 w = w1q[k * 16 + q];
                ffma2(acc[2 * q],     a, w.x);
                ffma2(acc[2 * q + 1], a, w.y);
            }
        }
#pragma unroll
        for (int n = 0; n < 32; n++) {
            float lo, hi; unpack2(acc[n], lo, hi);
            At[2 * n][tid]     = silu_f(lo);
            At[2 * n + 1][tid] = silu_f(hi);
        }
    }
    __syncthreads();

    const int g  = tid & 31;   // pair group: pairs 4g..4g+3
    const int c  = tid >> 5;   // chunk 0..3
    const int p0 = g * 4;

    // ---- phase 2: layer 2 GEMM, 4 pairs x 16 channels per thread ----
    unsigned long long acc2[4][8];   // acc2[p][m] = channels (16c+2m, 16c+2m+1)
    {
        const int n0q = c * 4;       // quad index of first channel
#pragma unroll
        for (int q = 0; q < 4; q++) {
            const ulonglong2 bv = b2q[n0q + q];
#pragma unroll
            for (int p = 0; p < 4; p++) {
                acc2[p][2 * q] = bv.x;  acc2[p][2 * q + 1] = bv.y;
            }
        }
#pragma unroll 4
        for (int k = 0; k < 64; k++) {
            const float4 a4 = *(const float4*)&At[k][p0];
            const unsigned long long a0 = pack2(a4.x, a4.x);
            const unsigned long long a1 = pack2(a4.y, a4.y);
            const unsigned long long a2 = pack2(a4.z, a4.z);
            const unsigned long long a3 = pack2(a4.w, a4.w);
#pragma unroll
            for (int q = 0; q < 4; q++) {
                const ulonglong2 w = w2q[k * 16 + n0q + q];
                ffma2(acc2[0][2 * q],     a0, w.x);  ffma2(acc2[0][2 * q + 1], a0, w.y);
                ffma2(acc2[1][2 * q],     a1, w.x);  ffma2(acc2[1][2 * q + 1], a1, w.y);
                ffma2(acc2[2][2 * q],     a2, w.x);  ffma2(acc2[2][2 * q + 1], a2, w.y);
                ffma2(acc2[3][2 * q],     a3, w.x);  ffma2(acc2[3][2 * q + 1], a3, w.y);
            }
        }
    }
    __syncthreads();   // all At reads done before overwrite

    // ---- SiLU + write layer-2 activations back into At ----
    {
#pragma unroll
        for (int m = 0; m < 8; m++) {
            float4 lo4, hi4;
            float l, h;
            unpack2(acc2[0][m], l, h); lo4.x = silu_f(l); hi4.x = silu_f(h);
            unpack2(acc2[1][m], l, h); lo4.y = silu_f(l); hi4.y = silu_f(h);
            unpack2(acc2[2][m], l, h); lo4.z = silu_f(l); hi4.z = silu_f(h);
            unpack2(acc2[3][m], l, h); lo4.w = silu_f(l); hi4.w = silu_f(h);
            const int n = c * 16 + 2 * m;
            *(float4*)&At[n][p0]     = lo4;
            *(float4*)&At[n + 1][p0] = hi4;
        }
    }
    __syncthreads();

    // ---- phase 3: layer 3 ([64]@[64,8]); 4 pairs x heads {2c, 2c+1} ----
    {
        unsigned long long acc3[4];
        const unsigned long long b3v = b3d[c];
#pragma unroll
        for (int p = 0; p < 4; p++) acc3[p] = b3v;
#pragma unroll 8
        for (int k = 0; k < 64; k++) {
            const float4 a4 = *(const float4*)&At[k][p0];
            const unsigned long long w = w3d[k * 4 + c];
            ffma2(acc3[0], pack2(a4.x, a4.x), w);
            ffma2(acc3[1], pack2(a4.y, a4.y), w);
            ffma2(acc3[2], pack2(a4.z, a4.z), w);
            ffma2(acc3[3], pack2(a4.w, a4.w), w);
        }
        float4 lo4, hi4;
        unpack2(acc3[0], lo4.x, hi4.x);
        unpack2(acc3[1], lo4.y, hi4.y);
        unpack2(acc3[2], lo4.z, hi4.z);
        unpack2(acc3[3], lo4.w, hi4.w);
        // out[((bb*8 + h)*S + i)*S + j], h = 2c (lo) and 2c+1 (hi)
        const size_t jbase = (size_t)blockIdx.x * 128 + p0;
        const size_t base  = (((size_t)bb * 8 + 2 * c) * S_DIM + i) * S_DIM + jbase;
        *(float4*)(out + base)                          = lo4;
        *(float4*)(out + base + (size_t)S_DIM * S_DIM)  = hi4;
    }
}

extern "C" void kernel_launch(void* const* d_in, const int* in_sizes, int n_in,
                              void* d_out, int out_size) {
    const float* coords = (const float*)d_in[0];
    const float* w1     = (const float*)d_in[1];
    const float* b1     = (const float*)d_in[2];
    const float* w2     = (const float*)d_in[3];
    const float* b2     = (const float*)d_in[4];
    const float* w3     = (const float*)d_in[5];
    const float* b3     = (const float*)d_in[6];
    float* out = (float*)d_out;

    dim3 grid(S_DIM / 128, S_DIM, 2);  // (j-tiles, i, b)
    shab_kernel<<<grid, 128>>>(coords, w1, b1, w2, b2, w3, b3, out);
}